// round 1
// baseline (speedup 1.0000x reference)
#include <cuda_runtime.h>
#include <cstdint>

#define D_    1024
#define DFF_  4096
#define B_    4
#define S_    2048
#define BS_   (B_ * S_)        // 8192 rows
#define EPS_  1e-6f
#define SLOPE_ 0.01f

// ---------------- scratch (device globals; no allocation allowed) ----------------
__device__ float g_q [BS_ * D_];
__device__ float g_k [BS_ * D_];
__device__ float g_v [BS_ * D_];
__device__ float g_sc[(long long)B_ * S_ * S_];   // 16,777,216
__device__ float g_ao[BS_ * D_];
__device__ float g_h [BS_ * D_];
__device__ float g_mid[(long long)BS_ * DFF_];

// ---------------- block reductions ----------------
__device__ __forceinline__ float warpRedMax(float v) {
    #pragma unroll
    for (int o = 16; o > 0; o >>= 1) v = fmaxf(v, __shfl_xor_sync(0xffffffffu, v, o));
    return v;
}
__device__ __forceinline__ float warpRedSum(float v) {
    #pragma unroll
    for (int o = 16; o > 0; o >>= 1) v += __shfl_xor_sync(0xffffffffu, v, o);
    return v;
}
__device__ float blockRedMax(float v) {
    __shared__ float sh[8];
    int lane = threadIdx.x & 31, wid = threadIdx.x >> 5;
    __syncthreads();
    v = warpRedMax(v);
    if (lane == 0) sh[wid] = v;
    __syncthreads();
    float r = sh[0];
    #pragma unroll
    for (int i = 1; i < 8; i++) r = fmaxf(r, sh[i]);
    return r;
}
__device__ float blockRedSum(float v) {
    __shared__ float sh[8];
    int lane = threadIdx.x & 31, wid = threadIdx.x >> 5;
    __syncthreads();
    v = warpRedSum(v);
    if (lane == 0) sh[wid] = v;
    __syncthreads();
    float r = 0.f;
    #pragma unroll
    for (int i = 0; i < 8; i++) r += sh[i];
    return r;
}

// ---------------- tiled SGEMM: C = alpha*(A@B) + bias, optional leaky-relu ----------------
// TB=0: B is [K,N] row-major.  TB=1: B is [N,K] row-major (C = A @ B^T).
// 128x128 tile, BK=8, 256 threads, 8x8 per thread in 2x2 fragments of 4x4.
#define BM 128
#define BN 128
#define BK 8

template<int TB, int ACT>
__global__ __launch_bounds__(256)
void gemm_kernel(const float* __restrict__ A, const float* __restrict__ Bm,
                 const float* __restrict__ bias, float* __restrict__ C,
                 int M, int N, int K,
                 long long sA, long long sB, long long sC, float alpha)
{
    const int z = blockIdx.z;
    A  += (long long)z * sA;
    Bm += (long long)z * sB;
    C  += (long long)z * sC;

    const int bm = blockIdx.y * BM;
    const int bn = blockIdx.x * BN;
    const int tid = threadIdx.x;
    const int tx = tid & 15;        // 0..15 -> columns
    const int ty = tid >> 4;        // 0..15 -> rows

    __shared__ float As[BK][BM];
    __shared__ float Bs[BK][BN];

    // A tile load: 128 rows x 8 k -> 2 float4 per row
    const int arow  = tid >> 1;
    const int acol4 = (tid & 1) * 4;
    const float* Aptr = A + (long long)(bm + arow) * K + acol4;

    const float* Bptr;
    int brow, bcol4;
    if (TB == 0) {
        // B tile: 8 k-rows x 128 n
        brow  = tid >> 5;             // 0..7 (k)
        bcol4 = (tid & 31) * 4;       // n
        Bptr = Bm + (long long)brow * N + bn + bcol4;
    } else {
        // B^T tile: 128 n-rows x 8 k
        brow  = tid >> 1;             // 0..127 (n)
        bcol4 = (tid & 1) * 4;        // k
        Bptr = Bm + (long long)(bn + brow) * K + bcol4;
    }

    float acc[8][8];
    #pragma unroll
    for (int i = 0; i < 8; i++)
        #pragma unroll
        for (int j = 0; j < 8; j++) acc[i][j] = 0.f;

    for (int k0 = 0; k0 < K; k0 += BK) {
        float4 a4 = *(const float4*)Aptr;
        float4 b4 = *(const float4*)Bptr;
        As[acol4 + 0][arow] = a4.x;
        As[acol4 + 1][arow] = a4.y;
        As[acol4 + 2][arow] = a4.z;
        As[acol4 + 3][arow] = a4.w;
        if (TB == 0) {
            *(float4*)&Bs[brow][bcol4] = b4;
        } else {
            Bs[bcol4 + 0][brow] = b4.x;
            Bs[bcol4 + 1][brow] = b4.y;
            Bs[bcol4 + 2][brow] = b4.z;
            Bs[bcol4 + 3][brow] = b4.w;
        }
        __syncthreads();

        #pragma unroll
        for (int k = 0; k < BK; k++) {
            float4 a0 = *(const float4*)&As[k][ty * 4];
            float4 a1 = *(const float4*)&As[k][ty * 4 + 64];
            float4 b0 = *(const float4*)&Bs[k][tx * 4];
            float4 b1 = *(const float4*)&Bs[k][tx * 4 + 64];
            float ar[8] = {a0.x, a0.y, a0.z, a0.w, a1.x, a1.y, a1.z, a1.w};
            float br[8] = {b0.x, b0.y, b0.z, b0.w, b1.x, b1.y, b1.z, b1.w};
            #pragma unroll
            for (int i = 0; i < 8; i++)
                #pragma unroll
                for (int j = 0; j < 8; j++)
                    acc[i][j] = fmaf(ar[i], br[j], acc[i][j]);
        }
        __syncthreads();

        Aptr += BK;
        if (TB == 0) Bptr += (long long)BK * N;
        else         Bptr += BK;
    }

    // epilogue
    #pragma unroll
    for (int ih = 0; ih < 2; ih++) {
        #pragma unroll
        for (int i = 0; i < 4; i++) {
            int row = bm + ih * 64 + ty * 4 + i;
            #pragma unroll
            for (int jh = 0; jh < 2; jh++) {
                int col = bn + jh * 64 + tx * 4;
                float4 v;
                v.x = acc[ih * 4 + i][jh * 4 + 0] * alpha;
                v.y = acc[ih * 4 + i][jh * 4 + 1] * alpha;
                v.z = acc[ih * 4 + i][jh * 4 + 2] * alpha;
                v.w = acc[ih * 4 + i][jh * 4 + 3] * alpha;
                if (bias != nullptr) {
                    float4 bb = *(const float4*)&bias[col];
                    v.x += bb.x; v.y += bb.y; v.z += bb.z; v.w += bb.w;
                }
                if (ACT == 1) {
                    v.x = v.x > 0.f ? v.x : SLOPE_ * v.x;
                    v.y = v.y > 0.f ? v.y : SLOPE_ * v.y;
                    v.z = v.z > 0.f ? v.z : SLOPE_ * v.z;
                    v.w = v.w > 0.f ? v.w : SLOPE_ * v.w;
                }
                *(float4*)&C[(long long)row * N + col] = v;
            }
        }
    }
}

// ---------------- softmax over last dim (S) + intensity add ----------------
__global__ __launch_bounds__(256)
void softmax_bias_kernel(const float* __restrict__ sc, const float* __restrict__ inten,
                         float* __restrict__ out)
{
    long long row = blockIdx.x;
    const float* s  = sc    + row * (long long)S_;
    const float* it = inten + row * (long long)S_;
    float*       o  = out   + row * (long long)S_;
    int tid = threadIdx.x;

    float v[8];
    float m = -1e30f;
    #pragma unroll
    for (int j = 0; j < 8; j++) { v[j] = s[tid + j * 256]; m = fmaxf(m, v[j]); }
    m = blockRedMax(m);

    float sum = 0.f;
    #pragma unroll
    for (int j = 0; j < 8; j++) { v[j] = __expf(v[j] - m); sum += v[j]; }
    sum = blockRedSum(sum);
    float inv = 1.f / sum;

    #pragma unroll
    for (int j = 0; j < 8; j++)
        o[tid + j * 256] = fmaf(v[j], inv, it[tid + j * 256]);
}

// ---------------- residual + layernorm ----------------
__global__ __launch_bounds__(256)
void residual_ln_kernel(const float* __restrict__ a, const float* __restrict__ b,
                        const float* __restrict__ g, const float* __restrict__ be,
                        float* __restrict__ out)
{
    long long row = blockIdx.x;
    int tid = threadIdx.x;
    const float4* pa = (const float4*)(a + row * (long long)D_);
    const float4* pb = (const float4*)(b + row * (long long)D_);
    float4 x = pa[tid];
    float4 y = pb[tid];
    x.x += y.x; x.y += y.y; x.z += y.z; x.w += y.w;

    float s  = x.x + x.y + x.z + x.w;
    float ss = x.x * x.x + x.y * x.y + x.z * x.z + x.w * x.w;
    s  = blockRedSum(s);
    ss = blockRedSum(ss);
    float mu  = s * (1.f / D_);
    float var = ss * (1.f / D_) - mu * mu;
    float r   = rsqrtf(var + EPS_);

    float4 gg = ((const float4*)g)[tid];
    float4 bb = ((const float4*)be)[tid];
    float4 o;
    o.x = (x.x - mu) * r * gg.x + bb.x;
    o.y = (x.y - mu) * r * gg.y + bb.y;
    o.z = (x.z - mu) * r * gg.z + bb.z;
    o.w = (x.w - mu) * r * gg.w + bb.w;
    ((float4*)(out + row * (long long)D_))[tid] = o;
}

// ---------------- launcher ----------------
extern "C" void kernel_launch(void* const* d_in, const int* in_sizes, int n_in,
                              void* d_out, int out_size)
{
    const float* X     = (const float*)d_in[0];
    const float* inten = (const float*)d_in[1];
    const float* Wq = (const float*)d_in[2];  const float* bq = (const float*)d_in[3];
    const float* Wk = (const float*)d_in[4];  const float* bk = (const float*)d_in[5];
    const float* Wv = (const float*)d_in[6];  const float* bv = (const float*)d_in[7];
    const float* Wo = (const float*)d_in[8];  const float* bo = (const float*)d_in[9];
    const float* W1 = (const float*)d_in[10]; const float* b1 = (const float*)d_in[11];
    const float* W2 = (const float*)d_in[12]; const float* b2 = (const float*)d_in[13];
    const float* g1 = (const float*)d_in[14]; const float* be1 = (const float*)d_in[15];
    const float* g2 = (const float*)d_in[16]; const float* be2 = (const float*)d_in[17];
    float* out = (float*)d_out;

    float *q, *k, *v, *sc, *ao, *h, *mid;
    cudaGetSymbolAddress((void**)&q,   g_q);
    cudaGetSymbolAddress((void**)&k,   g_k);
    cudaGetSymbolAddress((void**)&v,   g_v);
    cudaGetSymbolAddress((void**)&sc,  g_sc);
    cudaGetSymbolAddress((void**)&ao,  g_ao);
    cudaGetSymbolAddress((void**)&h,   g_h);
    cudaGetSymbolAddress((void**)&mid, g_mid);

    const long long SD = (long long)S_ * D_;       // 2097152
    const long long SS = (long long)S_ * S_;       // 4194304
    const float inv_sqrt_d = 0.03125f;             // 1/sqrt(1024)

    // QKV projections: [8192,1024] @ [1024,1024] + bias
    dim3 gProj(D_ / BN, BS_ / BM, 1);
    gemm_kernel<0, 0><<<gProj, 256>>>(X, Wq, bq, q, BS_, D_, D_, 0, 0, 0, 1.f);
    gemm_kernel<0, 0><<<gProj, 256>>>(X, Wk, bk, k, BS_, D_, D_, 0, 0, 0, 1.f);
    gemm_kernel<0, 0><<<gProj, 256>>>(X, Wv, bv, v, BS_, D_, D_, 0, 0, 0, 1.f);

    // scores = Q @ K^T / sqrt(D), batched over B
    dim3 gScore(S_ / BN, S_ / BM, B_);
    gemm_kernel<1, 0><<<gScore, 256>>>(q, k, nullptr, sc, S_, S_, D_, SD, SD, SS, inv_sqrt_d);

    // attn = softmax(scores) + intensity  (in-place per-row)
    softmax_bias_kernel<<<BS_, 256>>>(sc, inten, sc);

    // attn_out = attn @ V, batched over B
    dim3 gAV(D_ / BN, S_ / BM, B_);
    gemm_kernel<0, 0><<<gAV, 256>>>(sc, v, nullptr, ao, S_, D_, S_, SS, SD, SD, 1.f);

    // O projection (reuse q as scratch)
    gemm_kernel<0, 0><<<gProj, 256>>>(ao, Wo, bo, q, BS_, D_, D_, 0, 0, 0, 1.f);

    // h = LN(o + X)
    residual_ln_kernel<<<BS_, 256>>>(q, X, g1, be1, h);

    // FFN1: [8192,1024] @ [1024,4096] + b1, leaky relu
    dim3 gF1(DFF_ / BN, BS_ / BM, 1);
    gemm_kernel<0, 1><<<gF1, 256>>>(h, W1, b1, mid, BS_, DFF_, D_, 0, 0, 0, 1.f);

    // FFN2: [8192,4096] @ [4096,1024] + b2 (reuse k as scratch)
    gemm_kernel<0, 0><<<gProj, 256>>>(mid, W2, b2, k, BS_, D_, DFF_, 0, 0, 0, 1.f);

    // out = LN(ffn + h)
    residual_ln_kernel<<<BS_, 256>>>(k, h, g2, be2, out);
}

// round 5
// speedup vs baseline: 4.1647x; 4.1647x over previous
#include <cuda_runtime.h>
#include <cstdint>

#define D_    1024
#define DFF_  4096
#define B_    4
#define S_    2048
#define BS_   (B_ * S_)        // 8192 rows
#define EPS_  1e-6f
#define SLOPE_ 0.01f

// ---------------- scratch (device globals; no allocation allowed) ----------------
__device__ float g_xr [BS_ * D_];                 // rounded X (QKV A-operand)
__device__ float g_q  [BS_ * D_];
__device__ float g_k  [BS_ * D_];
__device__ float g_v  [BS_ * D_];
__device__ float g_vt [BS_ * D_];                 // V^T per batch [D,S]
__device__ float g_sc [(long long)B_ * S_ * S_];  // scores / attn
__device__ float g_ao [BS_ * D_];
__device__ float g_h  [BS_ * D_];
__device__ float g_hr [BS_ * D_];                 // rounded h (FFN1 A-operand)
__device__ float g_mid[(long long)BS_ * DFF_];
__device__ float g_wtq[D_ * D_];                  // transposed+rounded weights [N,K]
__device__ float g_wtk[D_ * D_];
__device__ float g_wtv[D_ * D_];
__device__ float g_wto[D_ * D_];
__device__ float g_wt1[(long long)D_ * DFF_];     // W1^T : [DFF, D]
__device__ float g_wt2[(long long)D_ * DFF_];     // W2^T : [D, DFF]

// ---------------- PTX helpers (portable ISA only: sm_80+ non-'a') ----------------
__device__ __forceinline__ uint32_t smem_to_u32(const void* smem_ptr) {
    uint32_t addr;
    asm("{ .reg .u64 tmp; cvta.to.shared.u64 tmp, %1; cvt.u32.u64 %0, tmp; }"
        : "=r"(addr) : "l"(smem_ptr));
    return addr;
}

#define CP_ASYNC16(saddr, gptr) \
    asm volatile("cp.async.cg.shared.global [%0], [%1], 16;" :: "r"(saddr), "l"(gptr))
#define CP_COMMIT() asm volatile("cp.async.commit_group;" ::: "memory")
#define CP_WAIT(n)  asm volatile("cp.async.wait_group %0;" :: "n"(n) : "memory")

#define LDSM_X4(r0, r1, r2, r3, addr) \
    asm volatile("ldmatrix.sync.aligned.m8n8.x4.shared.b16 {%0,%1,%2,%3}, [%4];" \
        : "=r"(r0), "=r"(r1), "=r"(r2), "=r"(r3) : "r"(addr))

__device__ __forceinline__ void mma_tf32(float* c, const uint32_t* a, const uint32_t* b) {
    asm volatile(
        "mma.sync.aligned.m16n8k8.row.col.f32.tf32.tf32.f32 "
        "{%0,%1,%2,%3}, {%4,%5,%6,%7}, {%8,%9}, {%0,%1,%2,%3};"
        : "+f"(c[0]), "+f"(c[1]), "+f"(c[2]), "+f"(c[3])
        : "r"(a[0]), "r"(a[1]), "r"(a[2]), "r"(a[3]), "r"(b[0]), "r"(b[1]));
}

__device__ __forceinline__ float rna_tf32(float x) {
    uint32_t u;
    asm("cvt.rna.tf32.f32 %0, %1;" : "=r"(u) : "f"(x));
    return __uint_as_float(u);
}

// ---------------- block reductions ----------------
__device__ __forceinline__ float warpRedMax(float v) {
    #pragma unroll
    for (int o = 16; o > 0; o >>= 1) v = fmaxf(v, __shfl_xor_sync(0xffffffffu, v, o));
    return v;
}
__device__ __forceinline__ float warpRedSum(float v) {
    #pragma unroll
    for (int o = 16; o > 0; o >>= 1) v += __shfl_xor_sync(0xffffffffu, v, o);
    return v;
}
__device__ float blockRedMax(float v) {
    __shared__ float sh[8];
    int lane = threadIdx.x & 31, wid = threadIdx.x >> 5;
    __syncthreads();
    v = warpRedMax(v);
    if (lane == 0) sh[wid] = v;
    __syncthreads();
    float r = sh[0];
    #pragma unroll
    for (int i = 1; i < 8; i++) r = fmaxf(r, sh[i]);
    return r;
}
__device__ float blockRedSum(float v) {
    __shared__ float sh[8];
    int lane = threadIdx.x & 31, wid = threadIdx.x >> 5;
    __syncthreads();
    v = warpRedSum(v);
    if (lane == 0) sh[wid] = v;
    __syncthreads();
    float r = 0.f;
    #pragma unroll
    for (int i = 0; i < 8; i++) r += sh[i];
    return r;
}

// ================= tf32 mma.sync GEMM =================
// C[M,N](+z*sC) = act( alpha * A[M,K](+z*sA) @ Bt[N,K]^T(+z*sB) + bias )
// 128x128 CTA tile, BK=32, 256 threads, 8 warps (2m x 4n), warp tile 64x32.
// 3-stage cp.async pipeline, SW128 swizzle, ldmatrix fragment loads.
#define STAGES 3
#define TILE_BYTES  (128 * 32 * 4)            // 16 KB (A or B tile)
#define STAGE_BYTES (2 * TILE_BYTES)          // 32 KB
#define GEMM_DSMEM  (STAGES * STAGE_BYTES + 1024)

__device__ __forceinline__ void load_chunk32(
    uint32_t sA_base, uint32_t sB_base,
    const float* __restrict__ gA, const float* __restrict__ gB,
    int K, int tid)
{
    #pragma unroll
    for (int j = 0; j < 4; j++) {
        int idx = j * 256 + tid;          // 0..1023 : 16B segments of a 16KB tile
        int row = idx >> 3;
        int seg = idx & 7;
        uint32_t off = (uint32_t)idx * 16u;
        uint32_t sw = off ^ ((off >> 3) & 0x70u);
        const float* ga = gA + (long long)row * K + seg * 4;
        const float* gb = gB + (long long)row * K + seg * 4;
        CP_ASYNC16(sA_base + sw, ga);
        CP_ASYNC16(sB_base + sw, gb);
    }
}

template<int ACT, int ROUND>
__global__ __launch_bounds__(256)
void mma_gemm(const float* __restrict__ A, const float* __restrict__ Bt,
              const float* __restrict__ bias, float* __restrict__ C,
              int M, int N, int K,
              long long sA, long long sB, long long sC, float alpha)
{
    extern __shared__ char smem_raw[];
    uint32_t smem_base = (smem_to_u32(smem_raw) + 1023u) & ~1023u;

    const int z = blockIdx.z;
    A  += (long long)z * sA;
    Bt += (long long)z * sB;
    C  += (long long)z * sC;

    const int bm = blockIdx.y * 128;
    const int bn = blockIdx.x * 128;
    const int tid  = threadIdx.x;
    const int lane = tid & 31;
    const int wid  = tid >> 5;
    const int wm = wid >> 2;            // 0..1 : 64-row slab
    const int wn = wid & 3;             // 0..3 : 32-col slab
    const int NK = K >> 5;

    // ---- ldmatrix per-thread swizzled base offsets ----
    const int g   = lane >> 3;          // ldsm address group
    const int rin = lane & 7;
    // A frags: x4 -> (a0,a1,a2,a3) = (r,c),(r+8,c),(r,c+4),(r+8,c+4)
    const int arow_off = ((g & 1) << 3) + rin;
    const int acol_off = (g >> 1) << 2;
    uint32_t aswb[4];
    #pragma unroll
    for (int mf = 0; mf < 4; mf++) {
        int row = wm * 64 + mf * 16 + arow_off;
        uint32_t off = (uint32_t)row * 128u + (uint32_t)acol_off * 4u;
        aswb[mf] = off ^ (((uint32_t)row & 7u) << 4);
    }
    // B frags: x4 over 16 n-rows -> (b0,b1) of n-frag p*16, (b0,b1) of p*16+8
    const int brow_off = ((g >> 1) << 3) + rin;
    const int bcol_off = (g & 1) << 2;
    uint32_t bswb[2];
    #pragma unroll
    for (int p = 0; p < 2; p++) {
        int nrow = wn * 32 + p * 16 + brow_off;
        uint32_t off = (uint32_t)nrow * 128u + (uint32_t)bcol_off * 4u;
        bswb[p] = off ^ (((uint32_t)nrow & 7u) << 4);
    }

    float c[4][4][4];
    #pragma unroll
    for (int i = 0; i < 4; i++)
        #pragma unroll
        for (int j = 0; j < 4; j++)
            #pragma unroll
            for (int r = 0; r < 4; r++) c[i][j][r] = 0.f;

    const float* gA0 = A  + (long long)bm * K;
    const float* gB0 = Bt + (long long)bn * K;

    // prologue: stages 0..STAGES-2
    #pragma unroll
    for (int s = 0; s < STAGES - 1; s++) {
        uint32_t sa = smem_base + s * STAGE_BYTES;
        load_chunk32(sa, sa + TILE_BYTES, gA0 + s * 32, gB0 + s * 32, K, tid);
        CP_COMMIT();
    }

    for (int kt = 0; kt < NK; kt++) {
        const int s = kt % STAGES;
        CP_WAIT(STAGES - 2);
        __syncthreads();

        // prefetch next stage (overwrites stage computed last iteration -> safe after barrier)
        const int ktn = kt + STAGES - 1;
        if (ktn < NK) {
            const int sn = ktn % STAGES;
            uint32_t sa = smem_base + sn * STAGE_BYTES;
            load_chunk32(sa, sa + TILE_BYTES, gA0 + (long long)ktn * 32, gB0 + (long long)ktn * 32, K, tid);
        }
        CP_COMMIT();

        const uint32_t sA = smem_base + s * STAGE_BYTES;
        const uint32_t sB = sA + TILE_BYTES;
        #pragma unroll
        for (int ks = 0; ks < 4; ks++) {
            uint32_t a[4][4];
            uint32_t bb[2][4];
            #pragma unroll
            for (int mf = 0; mf < 4; mf++)
                LDSM_X4(a[mf][0], a[mf][1], a[mf][2], a[mf][3], sA + (aswb[mf] ^ (ks << 5)));
            #pragma unroll
            for (int p = 0; p < 2; p++)
                LDSM_X4(bb[p][0], bb[p][1], bb[p][2], bb[p][3], sB + (bswb[p] ^ (ks << 5)));
            #pragma unroll
            for (int mf = 0; mf < 4; mf++)
                #pragma unroll
                for (int nf = 0; nf < 4; nf++)
                    mma_tf32(c[mf][nf], a[mf], &bb[nf >> 1][(nf & 1) * 2]);
        }
        __syncthreads();
    }

    // ---- epilogue ----
    const int r0base = bm + wm * 64 + (lane >> 2);
    const int c0base = bn + wn * 32 + (lane & 3) * 2;
    #pragma unroll
    for (int mf = 0; mf < 4; mf++) {
        #pragma unroll
        for (int nf = 0; nf < 4; nf++) {
            int col = c0base + nf * 8;
            float bx = 0.f, by = 0.f;
            if (bias != nullptr) { bx = bias[col]; by = bias[col + 1]; }
            #pragma unroll
            for (int half = 0; half < 2; half++) {
                int row = r0base + mf * 16 + half * 8;
                float vx = c[mf][nf][half * 2 + 0] * alpha + bx;
                float vy = c[mf][nf][half * 2 + 1] * alpha + by;
                if (ACT == 1) {
                    vx = vx > 0.f ? vx : SLOPE_ * vx;
                    vy = vy > 0.f ? vy : SLOPE_ * vy;
                }
                if (ROUND == 1) { vx = rna_tf32(vx); vy = rna_tf32(vy); }
                float2 o = make_float2(vx, vy);
                *(float2*)&C[(long long)row * N + col] = o;
            }
        }
    }
}

// ---------------- transpose (+ tf32 round): in [R,C] -> out [C,R] ----------------
__global__ __launch_bounds__(256)
void transpose_rna_kernel(const float* __restrict__ in, float* __restrict__ out,
                          int R, int Ccols, long long sIn, long long sOut)
{
    __shared__ float t[32][33];
    const int z = blockIdx.z;
    in  += (long long)z * sIn;
    out += (long long)z * sOut;
    const int c0 = blockIdx.x * 32;
    const int r0 = blockIdx.y * 32;
    const int tx = threadIdx.x & 31;
    const int ty = threadIdx.x >> 5;   // 0..7
    #pragma unroll
    for (int j = 0; j < 4; j++)
        t[ty + j * 8][tx] = in[(long long)(r0 + ty + j * 8) * Ccols + c0 + tx];
    __syncthreads();
    #pragma unroll
    for (int j = 0; j < 4; j++)
        out[(long long)(c0 + ty + j * 8) * R + r0 + tx] = rna_tf32(t[tx][ty + j * 8]);
}

// ---------------- round X to tf32 ----------------
__global__ __launch_bounds__(256)
void round_kernel(const float* __restrict__ in, float* __restrict__ out, int n4)
{
    int i = blockIdx.x * 256 + threadIdx.x;
    if (i < n4) {
        float4 v = ((const float4*)in)[i];
        v.x = rna_tf32(v.x); v.y = rna_tf32(v.y);
        v.z = rna_tf32(v.z); v.w = rna_tf32(v.w);
        ((float4*)out)[i] = v;
    }
}

// ---------------- softmax over last dim (S) + intensity add, rounded ----------------
__global__ __launch_bounds__(256)
void softmax_bias_kernel(const float* __restrict__ sc, const float* __restrict__ inten,
                         float* __restrict__ out)
{
    long long row = blockIdx.x;
    const float* s  = sc    + row * (long long)S_;
    const float* it = inten + row * (long long)S_;
    float*       o  = out   + row * (long long)S_;
    int tid = threadIdx.x;

    float v[8];
    float m = -1e30f;
    #pragma unroll
    for (int j = 0; j < 8; j++) { v[j] = s[tid + j * 256]; m = fmaxf(m, v[j]); }
    m = blockRedMax(m);

    float sum = 0.f;
    #pragma unroll
    for (int j = 0; j < 8; j++) { v[j] = __expf(v[j] - m); sum += v[j]; }
    sum = blockRedSum(sum);
    float inv = 1.f / sum;

    #pragma unroll
    for (int j = 0; j < 8; j++)
        o[tid + j * 256] = rna_tf32(fmaf(v[j], inv, it[tid + j * 256]));
}

// ---------------- residual + layernorm (optionally also writes rounded copy) ----------------
template<int WR>
__global__ __launch_bounds__(256)
void residual_ln_kernel(const float* __restrict__ a, const float* __restrict__ b,
                        const float* __restrict__ g, const float* __restrict__ be,
                        float* __restrict__ out, float* __restrict__ outr)
{
    long long row = blockIdx.x;
    int tid = threadIdx.x;
    const float4* pa = (const float4*)(a + row * (long long)D_);
    const float4* pb = (const float4*)(b + row * (long long)D_);
    float4 x = pa[tid];
    float4 y = pb[tid];
    x.x += y.x; x.y += y.y; x.z += y.z; x.w += y.w;

    float s  = x.x + x.y + x.z + x.w;
    float ss = x.x * x.x + x.y * x.y + x.z * x.z + x.w * x.w;
    s  = blockRedSum(s);
    ss = blockRedSum(ss);
    float mu  = s * (1.f / D_);
    float var = ss * (1.f / D_) - mu * mu;
    float r   = rsqrtf(var + EPS_);

    float4 gg = ((const float4*)g)[tid];
    float4 bb = ((const float4*)be)[tid];
    float4 o;
    o.x = (x.x - mu) * r * gg.x + bb.x;
    o.y = (x.y - mu) * r * gg.y + bb.y;
    o.z = (x.z - mu) * r * gg.z + bb.z;
    o.w = (x.w - mu) * r * gg.w + bb.w;
    ((float4*)(out + row * (long long)D_))[tid] = o;
    if (WR) {
        float4 orr;
        orr.x = rna_tf32(o.x); orr.y = rna_tf32(o.y);
        orr.z = rna_tf32(o.z); orr.w = rna_tf32(o.w);
        ((float4*)(outr + row * (long long)D_))[tid] = orr;
    }
}

// ---------------- launcher ----------------
extern "C" void kernel_launch(void* const* d_in, const int* in_sizes, int n_in,
                              void* d_out, int out_size)
{
    const float* X     = (const float*)d_in[0];
    const float* inten = (const float*)d_in[1];
    const float* Wq = (const float*)d_in[2];  const float* bq = (const float*)d_in[3];
    const float* Wk = (const float*)d_in[4];  const float* bk = (const float*)d_in[5];
    const float* Wv = (const float*)d_in[6];  const float* bv = (const float*)d_in[7];
    const float* Wo = (const float*)d_in[8];  const float* bo = (const float*)d_in[9];
    const float* W1 = (const float*)d_in[10]; const float* b1 = (const float*)d_in[11];
    const float* W2 = (const float*)d_in[12]; const float* b2 = (const float*)d_in[13];
    const float* g1 = (const float*)d_in[14]; const float* be1 = (const float*)d_in[15];
    const float* g2 = (const float*)d_in[16]; const float* be2 = (const float*)d_in[17];
    float* out = (float*)d_out;

    float *xr, *q, *k, *v, *vt, *sc, *ao, *h, *hr, *mid;
    float *wtq, *wtk, *wtv, *wto, *wt1, *wt2;
    cudaGetSymbolAddress((void**)&xr,  g_xr);
    cudaGetSymbolAddress((void**)&q,   g_q);
    cudaGetSymbolAddress((void**)&k,   g_k);
    cudaGetSymbolAddress((void**)&v,   g_v);
    cudaGetSymbolAddress((void**)&vt,  g_vt);
    cudaGetSymbolAddress((void**)&sc,  g_sc);
    cudaGetSymbolAddress((void**)&ao,  g_ao);
    cudaGetSymbolAddress((void**)&h,   g_h);
    cudaGetSymbolAddress((void**)&hr,  g_hr);
    cudaGetSymbolAddress((void**)&mid, g_mid);
    cudaGetSymbolAddress((void**)&wtq, g_wtq);
    cudaGetSymbolAddress((void**)&wtk, g_wtk);
    cudaGetSymbolAddress((void**)&wtv, g_wtv);
    cudaGetSymbolAddress((void**)&wto, g_wto);
    cudaGetSymbolAddress((void**)&wt1, g_wt1);
    cudaGetSymbolAddress((void**)&wt2, g_wt2);

    cudaFuncSetAttribute(mma_gemm<0,0>, cudaFuncAttributeMaxDynamicSharedMemorySize, GEMM_DSMEM);
    cudaFuncSetAttribute(mma_gemm<0,1>, cudaFuncAttributeMaxDynamicSharedMemorySize, GEMM_DSMEM);
    cudaFuncSetAttribute(mma_gemm<1,1>, cudaFuncAttributeMaxDynamicSharedMemorySize, GEMM_DSMEM);

    const long long SD = (long long)S_ * D_;
    const long long SS = (long long)S_ * S_;
    const float inv_sqrt_d = 0.03125f;

    // --- operand prep: round X; transpose+round weights ---
    round_kernel<<<(BS_ * D_ / 4 + 255) / 256, 256>>>(X, xr, BS_ * D_ / 4);
    dim3 tb(256);
    transpose_rna_kernel<<<dim3(D_/32, D_/32, 1), tb>>>(Wq, wtq, D_, D_, 0, 0);
    transpose_rna_kernel<<<dim3(D_/32, D_/32, 1), tb>>>(Wk, wtk, D_, D_, 0, 0);
    transpose_rna_kernel<<<dim3(D_/32, D_/32, 1), tb>>>(Wv, wtv, D_, D_, 0, 0);
    transpose_rna_kernel<<<dim3(D_/32, D_/32, 1), tb>>>(Wo, wto, D_, D_, 0, 0);
    transpose_rna_kernel<<<dim3(DFF_/32, D_/32, 1), tb>>>(W1, wt1, D_, DFF_, 0, 0);   // [D,DFF]->[DFF,D]
    transpose_rna_kernel<<<dim3(D_/32, DFF_/32, 1), tb>>>(W2, wt2, DFF_, D_, 0, 0);   // [DFF,D]->[D,DFF]

    // --- QKV projections (outputs rounded: GEMM operands downstream) ---
    dim3 gProj(D_ / 128, BS_ / 128, 1);
    mma_gemm<0,1><<<gProj, 256, GEMM_DSMEM>>>(xr, wtq, bq, q, BS_, D_, D_, 0, 0, 0, 1.f);
    mma_gemm<0,1><<<gProj, 256, GEMM_DSMEM>>>(xr, wtk, bk, k, BS_, D_, D_, 0, 0, 0, 1.f);
    mma_gemm<0,1><<<gProj, 256, GEMM_DSMEM>>>(xr, wtv, bv, v, BS_, D_, D_, 0, 0, 0, 1.f);

    // --- V^T per batch: [S,D] -> [D,S] ---
    transpose_rna_kernel<<<dim3(D_/32, S_/32, B_), tb>>>(v, vt, S_, D_, SD, SD);

    // --- scores = Q @ K^T / sqrt(D) ---
    dim3 gScore(S_ / 128, S_ / 128, B_);
    mma_gemm<0,0><<<gScore, 256, GEMM_DSMEM>>>(q, k, nullptr, sc, S_, S_, D_, SD, SD, SS, inv_sqrt_d);

    // --- attn = round(softmax(scores) + intensity) ---
    softmax_bias_kernel<<<BS_, 256>>>(sc, inten, sc);

    // --- attn_out = attn @ V  (B = Vt [D,S]); output rounded (O-proj operand) ---
    dim3 gAV(D_ / 128, S_ / 128, B_);
    mma_gemm<0,1><<<gAV, 256, GEMM_DSMEM>>>(sc, vt, nullptr, ao, S_, D_, S_, SS, SD, SD, 1.f);

    // --- O projection (reuse q) ---
    mma_gemm<0,0><<<gProj, 256, GEMM_DSMEM>>>(ao, wto, bo, q, BS_, D_, D_, 0, 0, 0, 1.f);

    // --- h = LN(o + X); also hr = round(h) ---
    residual_ln_kernel<1><<<BS_, 256>>>(q, X, g1, be1, h, hr);

    // --- FFN1: leaky(h @ W1 + b1), rounded ---
    dim3 gF1(DFF_ / 128, BS_ / 128, 1);
    mma_gemm<1,1><<<gF1, 256, GEMM_DSMEM>>>(hr, wt1, b1, mid, BS_, DFF_, D_, 0, 0, 0, 1.f);

    // --- FFN2 (reuse k) ---
    mma_gemm<0,0><<<gProj, 256, GEMM_DSMEM>>>(mid, wt2, b2, k, BS_, D_, DFF_, 0, 0, 0, 1.f);

    // --- out = LN(ffn + h) ---
    residual_ln_kernel<0><<<BS_, 256>>>(k, h, g2, be2, out, nullptr);
}